// round 11
// baseline (speedup 1.0000x reference)
#include <cuda_runtime.h>
#include <math.h>

#define Hd 512
#define Wd 512
#define NPTS 2048           // 64 segments * 32 samples
#define NT 512
#define RADIUS 10.0f        // sigma(-10) = 4.5e-5 truncation (rel_err floor ~6e-6)
#define E_LO 4.5399931e-5f  // e^{-RADIUS}
#define E_HI 22026.466f     // e^{+RADIUS}
#define NBIN 16             // 32-pixel bins, one per warp
#define CAP 128             // per-bin capacity

// Per-edge invariants, computed once: (x0, y0, dx, inv_dy). Masked: y0 = NaN.
__device__ float4 g_edge[NPTS];

__shared__ float2 s_bin[NBIN][CAP];   // 16 KB: (e^{32b - xc}, w) per bin
__shared__ int    s_cnt[NBIN];
__shared__ float  s_wc[NBIN + 1];     // full-weight buckets: wc[b] -> warps < b
__shared__ float  s_wcs[NBIN];        // suffix sums: wcs[j] = sum_{b>j} wc[b]

__device__ __forceinline__ float fsig(float z) {
    return __fdividef(1.0f, 1.0f + __expf(-z));
}

__device__ __forceinline__ float2 bez(const float2* c2, int idx) {
    int seg = idx >> 5;
    int k   = idx & 31;
    float t  = (float)k * (1.0f / 31.0f);
    float mt = 1.0f - t;
    float2 p0 = c2[3 * seg + 0];
    float2 p1 = c2[3 * seg + 1];
    float2 p2 = c2[3 * seg + 2];
    float2 p3 = c2[3 * seg + 3];
    float w0 = mt * mt * mt;
    float w1 = 3.0f * mt * mt * t;
    float w2 = 3.0f * mt * t * t;
    float w3 = t * t * t;
    return make_float2(w0 * p0.x + w1 * p1.x + w2 * p2.x + w3 * p3.x,
                       w0 * p0.y + w1 * p1.y + w2 * p2.y + w3 * p3.y);
}

// ---- Kernel 1: per-edge invariants; no smem, no sync, no atomics ----
__global__ __launch_bounds__(NT)
void build_edges(const float* __restrict__ cp) {
    const int e = blockIdx.x * NT + threadIdx.x;        // 0..2047
    const float2* c2 = (const float2*)cp;
    float2 a = bez(c2, e);
    float2 b = bez(c2, (e + 1) & (NPTS - 1));
    float dy = b.y - a.y;
    float y0 = a.y;
    float dyp = dy + 1e-8f;
    float invdy = 1.0f / dyp;
    if (fabsf(dy) < 1e-6f) {                            // reference mask==0
        y0 = __int_as_float(0x7fffffff);                // NaN -> band test rejects
        invdy = 1.0f;
    }
    g_edge[e] = make_float4(a.x, y0, b.x - a.x, invdy);
}

// ---- Kernel 2: one block per row; warp w owns pixels [32w, 32w+31] ----
__global__ __launch_bounds__(NT)
void render_row(const float* __restrict__ color, float* __restrict__ out) {
    const int tid  = threadIdx.x;
    const int lane = tid & 31;
    const int wp   = tid >> 5;
    const int y    = blockIdx.x;
    const float gy = (float)y;

    if (tid < NBIN) { s_cnt[tid] = 0; s_wc[tid] = 0.0f; }
    if (tid == 0) s_wc[NBIN] = 0.0f;
    const float ex = __expf((float)lane);               // e^{x - 32*wp}
    __syncthreads();

    // --- Phase A: 4 coalesced edge loads per thread ---
    #pragma unroll
    for (int j = 0; j < 4; ++j) {
        float4 E = g_edge[tid + j * NT];                // (x0, y0, dx, inv_dy)
        float t = (gy - E.y) * E.w;
        if (!(t >= -1.0f && t <= 2.0f)) continue;       // NaN-rejecting band
        // sig(20t)*sig(20-20t) with a single reciprocal
        float w = __fdividef(1.0f,
                 (1.0f + __expf(-20.0f * t)) * (1.0f + __expf(20.0f * t - 20.0f)));
        w = copysignf(w, E.w);                          // sign(dy)
        float xc = fmaf(t, E.z, E.x);

        int b0r = (int)floorf((xc - RADIUS) * (1.0f / 32.0f));
        int b1r = (int)floorf((xc + RADIUS) * (1.0f / 32.0f));
        if (b1r < 0) continue;                          // fully left: zero
        if (b0r >= NBIN) {                              // fully right: all full
            atomicAdd(&s_wc[NBIN], w);
            continue;
        }
        if (b0r > 0) atomicAdd(&s_wc[b0r], w);          // warps < b0r get w
        int b0 = max(b0r, 0);
        int b1 = min(b1r, NBIN - 1);
        for (int bb = b0; bb <= b1; ++bb) {
            int q = atomicAdd(&s_cnt[bb], 1);
            if (q < CAP)                                // val = e^{32*bb - xc}
                s_bin[bb][q] = make_float2(__expf((float)(bb << 5) - xc), w);
        }
    }
    __syncthreads();

    // --- warp 0: suffix-scan the 16 buckets while others start Phase B ---
    if (wp == 0 && lane < NBIN) {
        float v = s_wc[lane + 1];
        #pragma unroll
        for (int o = 1; o < NBIN; o <<= 1) {
            float nb = __shfl_down_sync(0x0000ffffu, v, o);
            if (lane + o < NBIN) v += nb;
        }
        s_wcs[lane] = v;            // wcs[j] = sum_{b > j} wc[b]
    }

    // --- Phase B: u = ex*val = e^{x-xc}; sigma = 1/(1+u); no exp in loop ---
    float wind = 0.0f;
    {
        int m = min(s_cnt[wp], CAP);
        for (int i = 0; i < m; ++i) {
            float2 E = s_bin[wp][i];                    // (val, w) broadcast LDS
            float u = ex * E.x;
            if (u < E_LO)       wind += E.y;            // z > R: full weight
            else if (u <= E_HI) wind += __fdividef(E.y, 1.0f + u);
        }
    }
    __syncthreads();

    // --- combine + output ---
    wind += s_wcs[wp];
    float alpha = fsig(4.0f * wind);
    float cr = __ldg(&color[0]), cg = __ldg(&color[1]), cb = __ldg(&color[2]);
    ((float4*)out)[y * Wd + tid] = make_float4(cr, cg, cb, alpha);
}

extern "C" void kernel_launch(void* const* d_in, const int* in_sizes, int n_in,
                              void* d_out, int out_size) {
    (void)in_sizes; (void)n_in; (void)out_size;
    const float* cp    = (const float*)d_in[0];   // (193,2) float32
    const float* color = (const float*)d_in[1];   // (3,)    float32
    float* out = (float*)d_out;                   // (512,512,4) float32
    build_edges<<<NPTS / NT, NT>>>(cp);           // 4 blocks, no atomics
    render_row<<<Hd, NT>>>(color, out);
}

// round 12
// speedup vs baseline: 1.2178x; 1.2178x over previous
#include <cuda_runtime.h>
#include <math.h>

#define Hd 512
#define Wd 512
#define NPTS 2048           // 64 segments * 32 samples
#define NT 512
#define RADIUS 10.0f        // window half-width for carry split
#define E32 7.8962960e13f   // e^{32}
#define NBIN 16             // 32-pixel bins, one per warp
#define CAP 128             // per-bin capacity

// Per-edge invariants, computed once: (x0, y0, dx, inv_dy). Masked: y0 = NaN.
__device__ float4 g_edge[NPTS];

__shared__ float2 s_bin[NBIN][CAP];   // 16 KB: (e^{32b - xc}, w) per bin
__shared__ int    s_cnt[NBIN];
__shared__ float  s_wc[NBIN + 1];     // full-weight buckets: wc[b] -> warps < b
__shared__ float  s_wcs[NBIN];        // suffix sums: wcs[j] = sum_{b>j} wc[b]

__device__ __forceinline__ float fsig(float z) {
    return __fdividef(1.0f, 1.0f + __expf(-z));
}

__device__ __forceinline__ float2 bez(const float2* c2, int idx) {
    int seg = idx >> 5;
    int k   = idx & 31;
    float t  = (float)k * (1.0f / 31.0f);
    float mt = 1.0f - t;
    float2 p0 = c2[3 * seg + 0];
    float2 p1 = c2[3 * seg + 1];
    float2 p2 = c2[3 * seg + 2];
    float2 p3 = c2[3 * seg + 3];
    float w0 = mt * mt * mt;
    float w1 = 3.0f * mt * mt * t;
    float w2 = 3.0f * mt * t * t;
    float w3 = t * t * t;
    return make_float2(w0 * p0.x + w1 * p1.x + w2 * p2.x + w3 * p3.x,
                       w0 * p0.y + w1 * p1.y + w2 * p2.y + w3 * p3.y);
}

// ---- Kernel 1: per-edge invariants; no smem, no sync, no atomics ----
__global__ __launch_bounds__(NT)
void build_edges(const float* __restrict__ cp) {
    const int e = blockIdx.x * NT + threadIdx.x;        // 0..2047
    const float2* c2 = (const float2*)cp;
    float2 a = bez(c2, e);
    float2 b = bez(c2, (e + 1) & (NPTS - 1));
    float dy = b.y - a.y;
    float y0 = a.y;
    float dyp = dy + 1e-8f;
    float invdy = 1.0f / dyp;
    if (fabsf(dy) < 1e-6f) {                            // reference mask==0
        y0 = __int_as_float(0x7fffffff);                // NaN -> band test rejects
        invdy = 1.0f;
    }
    g_edge[e] = make_float4(a.x, y0, b.x - a.x, invdy);
}

// ---- Kernel 2: one block per row; warp w owns pixels [32w, 32w+31] ----
__global__ __launch_bounds__(NT)
void render_row(const float* __restrict__ color, float* __restrict__ out) {
    const int tid  = threadIdx.x;
    const int lane = tid & 31;
    const int wp   = tid >> 5;
    const int y    = blockIdx.x;
    const float gy = (float)y;

    if (tid < NBIN) { s_cnt[tid] = 0; s_wc[tid] = 0.0f; }
    if (tid == 0) s_wc[NBIN] = 0.0f;
    const float ex = __expf((float)lane);               // e^{x - 32*wp}
    __syncthreads();

    // --- Phase A: 4 coalesced edge loads per thread ---
    #pragma unroll
    for (int j = 0; j < 4; ++j) {
        float4 E = g_edge[tid + j * NT];                // (x0, y0, dx, inv_dy)
        float t = (gy - E.y) * E.w;
        if (!(t >= -1.0f && t <= 2.0f)) continue;       // NaN-rejecting band
        // sig(20t)*sig(20-20t) with a single reciprocal
        float w = __fdividef(1.0f,
                 (1.0f + __expf(-20.0f * t)) * (1.0f + __expf(20.0f * t - 20.0f)));
        w = copysignf(w, E.w);                          // sign(dy)
        float xc = fmaf(t, E.z, E.x);

        int b0r = (int)floorf((xc - RADIUS) * (1.0f / 32.0f));
        int b1r = (int)floorf((xc + RADIUS) * (1.0f / 32.0f));
        if (b1r < 0) continue;                          // fully left: zero
        if (b0r >= NBIN) {                              // fully right: all full
            atomicAdd(&s_wc[NBIN], w);
            continue;
        }
        if (b0r > 0) atomicAdd(&s_wc[b0r], w);          // warps < b0r get w
        int b0 = max(b0r, 0);
        int b1 = min(b1r, NBIN - 1);
        float val = __expf((float)(b0 << 5) - xc);      // e^{32*b0 - xc}
        for (int bb = b0; bb <= b1; ++bb) {
            int q = atomicAdd(&s_cnt[bb], 1);
            if (q < CAP) s_bin[bb][q] = make_float2(val, w);
            val *= E32;                                 // next bin: * e^{32}
        }
    }
    __syncthreads();

    // --- warp 0: suffix-scan the 16 buckets while others start Phase B ---
    if (wp == 0 && lane < NBIN) {
        float v = s_wc[lane + 1];
        #pragma unroll
        for (int o = 1; o < NBIN; o <<= 1) {
            float nb = __shfl_down_sync(0x0000ffffu, v, o);
            if (lane + o < NBIN) v += nb;
        }
        s_wcs[lane] = v;            // wcs[j] = sum_{b > j} wc[b]
    }

    // --- Phase B: branch-free: wind += w / (1 + e^{x-xc}) ---
    // u tiny  -> adds ~w   (matches full-weight carry semantics)
    // u huge  -> adds ~0   (outside window)
    float wind = 0.0f;
    {
        int m = min(s_cnt[wp], CAP);
        for (int i = 0; i < m; ++i) {
            float2 E = s_bin[wp][i];                    // (val, w) broadcast LDS
            wind += __fdividef(E.y, fmaf(ex, E.x, 1.0f));
        }
    }
    __syncthreads();

    // --- combine + output ---
    wind += s_wcs[wp];
    float alpha = fsig(4.0f * wind);
    float cr = __ldg(&color[0]), cg = __ldg(&color[1]), cb = __ldg(&color[2]);
    ((float4*)out)[y * Wd + tid] = make_float4(cr, cg, cb, alpha);
}

extern "C" void kernel_launch(void* const* d_in, const int* in_sizes, int n_in,
                              void* d_out, int out_size) {
    (void)in_sizes; (void)n_in; (void)out_size;
    const float* cp    = (const float*)d_in[0];   // (193,2) float32
    const float* color = (const float*)d_in[1];   // (3,)    float32
    float* out = (float*)d_out;                   // (512,512,4) float32
    build_edges<<<NPTS / NT, NT>>>(cp);           // 4 blocks, no atomics
    render_row<<<Hd, NT>>>(color, out);
}

// round 13
// speedup vs baseline: 1.3034x; 1.0702x over previous
#include <cuda_runtime.h>
#include <math.h>

#define Hd 512
#define Wd 512
#define NPTS 2048           // 64 segments * 32 samples
#define NT 512
#define RADIUS 10.0f        // carry/window split half-width
#define E32 7.8962960e13f   // e^{32}
#define NBIN 16             // 32-pixel bins, one per warp
#define CAP 128             // per-bin capacity

// Per-edge invariants, computed once: (x0, y0, dx, inv_dy). Masked: y0 = NaN.
__device__ float4 g_edge[NPTS];

__shared__ float2 s_bin[NBIN][CAP];   // 16 KB: (e^{32b - xc}, w) per bin
__shared__ int    s_cnt[NBIN];
__shared__ float  s_wc[NBIN + 1];     // full-weight buckets: wc[b] -> warps < b
__shared__ float  s_wcs[NBIN];        // suffix sums: wcs[j] = sum_{b>j} wc[b]

__device__ __forceinline__ float fsig(float z) {
    return __fdividef(1.0f, 1.0f + __expf(-z));
}

__device__ __forceinline__ float2 bez(const float2* c2, int idx) {
    int seg = idx >> 5;
    int k   = idx & 31;
    float t  = (float)k * (1.0f / 31.0f);
    float mt = 1.0f - t;
    float2 p0 = c2[3 * seg + 0];
    float2 p1 = c2[3 * seg + 1];
    float2 p2 = c2[3 * seg + 2];
    float2 p3 = c2[3 * seg + 3];
    float w0 = mt * mt * mt;
    float w1 = 3.0f * mt * mt * t;
    float w2 = 3.0f * mt * t * t;
    float w3 = t * t * t;
    return make_float2(w0 * p0.x + w1 * p1.x + w2 * p2.x + w3 * p3.x,
                       w0 * p0.y + w1 * p1.y + w2 * p2.y + w3 * p3.y);
}

// ---- Kernel 1: per-edge invariants; no smem, no sync, no atomics ----
__global__ __launch_bounds__(NT)
void build_edges(const float* __restrict__ cp) {
    const int e = blockIdx.x * NT + threadIdx.x;        // 0..2047
    const float2* c2 = (const float2*)cp;
    float2 a = bez(c2, e);
    float2 b = bez(c2, (e + 1) & (NPTS - 1));
    float dy = b.y - a.y;
    float y0 = a.y;
    float dyp = dy + 1e-8f;
    float invdy = 1.0f / dyp;
    if (fabsf(dy) < 1e-6f) {                            // reference mask==0
        y0 = __int_as_float(0x7fffffff);                // NaN -> band test rejects
        invdy = 1.0f;
    }
    g_edge[e] = make_float4(a.x, y0, b.x - a.x, invdy);
}

// ---- Kernel 2: one block per row; warp w owns pixels [32w, 32w+31] ----
__global__ __launch_bounds__(NT)
void render_row(const float* __restrict__ color, float* __restrict__ out) {
    const int tid  = threadIdx.x;
    const int lane = tid & 31;
    const int wp   = tid >> 5;
    const int y    = blockIdx.x;
    const float gy = (float)y;

    if (tid < NBIN) { s_cnt[tid] = 0; s_wc[tid] = 0.0f; }
    if (tid == 0) s_wc[NBIN] = 0.0f;
    const float ex = __expf((float)lane);               // e^{x - 32*wp}
    __syncthreads();

    // --- Phase A: 4 coalesced edge loads per thread ---
    #pragma unroll
    for (int j = 0; j < 4; ++j) {
        float4 E = g_edge[tid + j * NT];                // (x0, y0, dx, inv_dy)
        float t = (gy - E.y) * E.w;
        // band [-0.5, 1.5]: boundary weight sig(-10)=4.5e-5; NaN-rejecting
        if (!(t >= -0.5f && t <= 1.5f)) continue;
        // product of two sigmoids ~= sigmoid of the nearer boundary here
        float w = fsig(20.0f * fminf(t, 1.0f - t));
        w = copysignf(w, E.w);                          // sign(dy)
        float xc = fmaf(t, E.z, E.x);

        int b0r = (int)floorf((xc - RADIUS) * (1.0f / 32.0f));
        int b1r = (int)floorf((xc + RADIUS) * (1.0f / 32.0f));
        if (b1r < 0) continue;                          // fully left: zero
        if (b0r >= NBIN) {                              // fully right: all full
            atomicAdd(&s_wc[NBIN], w);
            continue;
        }
        if (b0r > 0) atomicAdd(&s_wc[b0r], w);          // warps < b0r get w
        int b0 = max(b0r, 0);
        int b1 = min(b1r, NBIN - 1);
        float val = __expf((float)(b0 << 5) - xc);      // e^{32*b0 - xc}
        for (int bb = b0; bb <= b1; ++bb) {
            int q = atomicAdd(&s_cnt[bb], 1);
            if (q < CAP) s_bin[bb][q] = make_float2(val, w);
            val *= E32;                                 // next bin: * e^{32}
        }
    }
    __syncthreads();

    // --- warp 0: suffix-scan the 16 buckets while others start Phase B ---
    if (wp == 0 && lane < NBIN) {
        float v = s_wc[lane + 1];
        #pragma unroll
        for (int o = 1; o < NBIN; o <<= 1) {
            float nb = __shfl_down_sync(0x0000ffffu, v, o);
            if (lane + o < NBIN) v += nb;
        }
        s_wcs[lane] = v;            // wcs[j] = sum_{b > j} wc[b]
    }

    // --- Phase B: branch-free wind += w/(1 + e^{x-xc}); 2-wide via LDS.128 ---
    float wind = 0.0f, wind2 = 0.0f;
    {
        int m = min(s_cnt[wp], CAP);
        const float4* bin4 = (const float4*)&s_bin[wp][0];
        int m2 = m >> 1;
        for (int i = 0; i < m2; ++i) {
            float4 E = bin4[i];                         // two (val,w) entries
            wind  += __fdividef(E.y, fmaf(ex, E.x, 1.0f));
            wind2 += __fdividef(E.w, fmaf(ex, E.z, 1.0f));
        }
        if (m & 1) {
            float2 E = s_bin[wp][m - 1];
            wind += __fdividef(E.y, fmaf(ex, E.x, 1.0f));
        }
    }
    __syncthreads();

    // --- combine + output ---
    wind += wind2 + s_wcs[wp];
    float alpha = fsig(4.0f * wind);
    float cr = __ldg(&color[0]), cg = __ldg(&color[1]), cb = __ldg(&color[2]);
    ((float4*)out)[y * Wd + tid] = make_float4(cr, cg, cb, alpha);
}

extern "C" void kernel_launch(void* const* d_in, const int* in_sizes, int n_in,
                              void* d_out, int out_size) {
    (void)in_sizes; (void)n_in; (void)out_size;
    const float* cp    = (const float*)d_in[0];   // (193,2) float32
    const float* color = (const float*)d_in[1];   // (3,)    float32
    float* out = (float*)d_out;                   // (512,512,4) float32
    build_edges<<<NPTS / NT, NT>>>(cp);           // 4 blocks, no atomics
    render_row<<<Hd, NT>>>(color, out);
}

// round 14
// speedup vs baseline: 1.3488x; 1.0349x over previous
#include <cuda_runtime.h>
#include <math.h>

#define Hd 512
#define Wd 512
#define NPTS 2048           // 64 segments * 32 samples
#define NT 512
#define RADIUS 10.0f        // carry/window split half-width
#define E32 7.8962960e13f   // e^{32}
#define NBIN 16             // 32-pixel bins, one per warp
#define CAP 128             // per-bin capacity

__shared__ float2 s_bin[NBIN][CAP];   // 16 KB: (e^{32b - xc}, w) per bin
__shared__ int    s_cnt[NBIN];
__shared__ float  s_wc[NBIN + 1];     // full-weight buckets: wc[b] -> warps < b
__shared__ float  s_wcs[NBIN];        // suffix sums: wcs[j] = sum_{b>j} wc[b]

__device__ __forceinline__ float fsig(float z) {
    return __fdividef(1.0f, 1.0f + __expf(-z));
}

__device__ __forceinline__ float2 bez(const float2* c2, int idx) {
    int seg = idx >> 5;
    int k   = idx & 31;
    float t  = (float)k * (1.0f / 31.0f);
    float mt = 1.0f - t;
    float2 p0 = c2[3 * seg + 0];
    float2 p1 = c2[3 * seg + 1];
    float2 p2 = c2[3 * seg + 2];
    float2 p3 = c2[3 * seg + 3];
    float w0 = mt * mt * mt;
    float w1 = 3.0f * mt * mt * t;
    float w2 = 3.0f * mt * t * t;
    float w3 = t * t * t;
    return make_float2(w0 * p0.x + w1 * p1.x + w2 * p2.x + w3 * p3.x,
                       w0 * p0.y + w1 * p1.y + w2 * p2.y + w3 * p3.y);
}

// Single fused kernel: one block per row; warp w owns pixels [32w, 32w+31].
__global__ __launch_bounds__(NT)
void render_row(const float* __restrict__ cp,
                const float* __restrict__ color,
                float* __restrict__ out) {
    const int tid  = threadIdx.x;
    const int lane = tid & 31;
    const int wp   = tid >> 5;
    const int y    = blockIdx.x;
    const float gy = (float)y;
    const float2* c2 = (const float2*)cp;

    if (tid < NBIN) { s_cnt[tid] = 0; s_wc[tid] = 0.0f; }
    if (tid == 0) s_wc[NBIN] = 0.0f;
    const float ex = __expf((float)lane);               // e^{x - 32*wp}
    __syncthreads();

    // --- Phase A: thread owns edges 4t..4t+3 (5 shared Bezier samples) ---
    {
        float2 p[5];
        #pragma unroll
        for (int k = 0; k < 5; ++k) p[k] = bez(c2, (4 * tid + k) & (NPTS - 1));
        #pragma unroll
        for (int j = 0; j < 4; ++j) {
            float2 a = p[j], b = p[j + 1];
            float dy = b.y - a.y;
            if (fabsf(dy) < 1e-6f) continue;            // reference mask==0
            float dyp = dy + 1e-8f;
            float t = (gy - a.y) * __fdividef(1.0f, dyp);
            // band [-0.5, 1.5]: boundary weight sig(-10)=4.5e-5
            if (!(t >= -0.5f && t <= 1.5f)) continue;
            // product of two sigmoids ~= sigmoid of the nearer boundary here
            float w = fsig(20.0f * fminf(t, 1.0f - t));
            w = (dyp > 0.0f) ? w : -w;                  // sign(dy)
            float xc = fmaf(t, b.x - a.x, a.x);

            int b0r = (int)floorf((xc - RADIUS) * (1.0f / 32.0f));
            int b1r = (int)floorf((xc + RADIUS) * (1.0f / 32.0f));
            if (b1r < 0) continue;                      // fully left: zero
            if (b0r >= NBIN) {                          // fully right: all full
                atomicAdd(&s_wc[NBIN], w);
                continue;
            }
            if (b0r > 0) atomicAdd(&s_wc[b0r], w);      // warps < b0r get w
            int b0 = max(b0r, 0);
            int b1 = min(b1r, NBIN - 1);
            float val = __expf((float)(b0 << 5) - xc);  // e^{32*b0 - xc}
            for (int bb = b0; bb <= b1; ++bb) {
                int q = atomicAdd(&s_cnt[bb], 1);
                if (q < CAP) s_bin[bb][q] = make_float2(val, w);
                val *= E32;                             // next bin: * e^{32}
            }
        }
    }
    __syncthreads();

    // --- warp 0: suffix-scan the 16 buckets while others start Phase B ---
    if (wp == 0 && lane < NBIN) {
        float v = s_wc[lane + 1];
        #pragma unroll
        for (int o = 1; o < NBIN; o <<= 1) {
            float nb = __shfl_down_sync(0x0000ffffu, v, o);
            if (lane + o < NBIN) v += nb;
        }
        s_wcs[lane] = v;            // wcs[j] = sum_{b > j} wc[b]
    }

    // --- Phase B: branch-free wind += w/(1 + e^{x-xc}); 2-wide via LDS.128 ---
    float wind = 0.0f, wind2 = 0.0f;
    {
        int m = min(s_cnt[wp], CAP);
        const float4* bin4 = (const float4*)&s_bin[wp][0];
        int m2 = m >> 1;
        for (int i = 0; i < m2; ++i) {
            float4 E = bin4[i];                         // two (val,w) entries
            wind  += __fdividef(E.y, fmaf(ex, E.x, 1.0f));
            wind2 += __fdividef(E.w, fmaf(ex, E.z, 1.0f));
        }
        if (m & 1) {
            float2 E = s_bin[wp][m - 1];
            wind += __fdividef(E.y, fmaf(ex, E.x, 1.0f));
        }
    }
    __syncthreads();

    // --- combine + output ---
    wind += wind2 + s_wcs[wp];
    float alpha = fsig(4.0f * wind);
    float cr = __ldg(&color[0]), cg = __ldg(&color[1]), cb = __ldg(&color[2]);
    ((float4*)out)[y * Wd + tid] = make_float4(cr, cg, cb, alpha);
}

extern "C" void kernel_launch(void* const* d_in, const int* in_sizes, int n_in,
                              void* d_out, int out_size) {
    (void)in_sizes; (void)n_in; (void)out_size;
    const float* cp    = (const float*)d_in[0];   // (193,2) float32
    const float* color = (const float*)d_in[1];   // (3,)    float32
    float* out = (float*)d_out;                   // (512,512,4) float32
    render_row<<<Hd, NT>>>(cp, color, out);
}

// round 16
// speedup vs baseline: 1.3851x; 1.0269x over previous
#include <cuda_runtime.h>
#include <math.h>

#define Hd 512
#define Wd 512
#define NSEG 64             // cubic segments
#define NT 512
#define RADIUS 10.0f        // carry/window split half-width
#define E32 7.8962960e13f   // e^{32}
#define NBIN 16             // 32-pixel bins, one per warp
#define CAP 128             // per-bin capacity

__shared__ __align__(16) float2 s_bin[NBIN][CAP];  // 16 KB: (e^{32b - xc}, w)
__shared__ float2 s_cp[194];          // control points (padded to 16B multiple)
__shared__ int    s_cnt[NBIN];
__shared__ float  s_wc[NBIN + 1];     // full-weight buckets: wc[b] -> warps < b
__shared__ float  s_wcs[NBIN];        // suffix sums: wcs[j] = sum_{b>j} wc[b]

__device__ __forceinline__ float fsig(float z) {
    return __fdividef(1.0f, 1.0f + __expf(-z));
}

// Single fused kernel: one block per row; warp w owns pixels [32w, 32w+31].
__global__ __launch_bounds__(NT)
void render_row(const float* __restrict__ cp,
                const float* __restrict__ color,
                float* __restrict__ out) {
    const int tid  = threadIdx.x;
    const int lane = tid & 31;
    const int wp   = tid >> 5;
    const int y    = blockIdx.x;
    const float gy = (float)y;

    if (tid < 193) s_cp[tid] = ((const float2*)cp)[tid];
    if (tid < NBIN) { s_cnt[tid] = 0; s_wc[tid] = 0.0f; }
    if (tid == 0) s_wc[NBIN] = 0.0f;
    const float ex = __expf((float)lane);               // e^{x - 32*wp}

    // per-lane Bernstein weights at t = lane/31 (same formula as reference)
    const float tb  = (float)lane * (1.0f / 31.0f);
    const float mtb = 1.0f - tb;
    const float bw0 = mtb * mtb * mtb;
    const float bw1 = 3.0f * mtb * mtb * tb;
    const float bw2 = 3.0f * mtb * tb * tb;
    const float bw3 = tb * tb * tb;
    __syncthreads();

    // --- Phase A: warp owns segments 4wp..4wp+3; lane l owns edge 32s+l ---
    #pragma unroll
    for (int it = 0; it < 4; ++it) {
        const int s = (wp << 2) + it;                   // segment 0..63
        float2 P0 = s_cp[3 * s + 0];
        float2 P1 = s_cp[3 * s + 1];
        float2 P2 = s_cp[3 * s + 2];
        float2 P3 = s_cp[3 * s + 3];
        float2 a = make_float2(
            bw0 * P0.x + bw1 * P1.x + bw2 * P2.x + bw3 * P3.x,
            bw0 * P0.y + bw1 * P1.y + bw2 * P2.y + bw3 * P3.y);
        float2 b;
        b.x = __shfl_down_sync(0xffffffffu, a.x, 1);
        b.y = __shfl_down_sync(0xffffffffu, a.y, 1);
        if (lane == 31) b = (s == NSEG - 1) ? s_cp[0] : a;  // closing / degenerate

        float dy = b.y - a.y;
        if (fabsf(dy) < 1e-6f) continue;                // reference mask==0
        float dyp = dy + 1e-8f;
        float t = (gy - a.y) * __fdividef(1.0f, dyp);
        // band [-0.5, 1.5]: boundary weight sig(-10)=4.5e-5
        if (!(t >= -0.5f && t <= 1.5f)) continue;
        // product of two sigmoids ~= sigmoid of the nearer boundary here
        float w = fsig(20.0f * fminf(t, 1.0f - t));
        w = (dyp > 0.0f) ? w : -w;                      // sign(dy)
        float xc = fmaf(t, b.x - a.x, a.x);

        int b0r = (int)floorf((xc - RADIUS) * (1.0f / 32.0f));
        int b1r = (int)floorf((xc + RADIUS) * (1.0f / 32.0f));
        if (b1r < 0) continue;                          // fully left: zero
        if (b0r >= NBIN) {                              // fully right: all full
            atomicAdd(&s_wc[NBIN], w);
            continue;
        }
        if (b0r > 0) atomicAdd(&s_wc[b0r], w);          // warps < b0r get w
        int b0 = max(b0r, 0);
        int b1 = min(b1r, NBIN - 1);
        float val = __expf((float)(b0 << 5) - xc);      // e^{32*b0 - xc}
        for (int bb = b0; bb <= b1; ++bb) {
            int q = atomicAdd(&s_cnt[bb], 1);
            if (q < CAP) s_bin[bb][q] = make_float2(val, w);
            val *= E32;                                 // next bin: * e^{32}
        }
    }
    __syncthreads();

    // --- warp 0: suffix-scan the 16 buckets while others start Phase B ---
    if (wp == 0 && lane < NBIN) {
        float v = s_wc[lane + 1];
        #pragma unroll
        for (int o = 1; o < NBIN; o <<= 1) {
            float nb = __shfl_down_sync(0x0000ffffu, v, o);
            if (lane + o < NBIN) v += nb;
        }
        s_wcs[lane] = v;            // wcs[j] = sum_{b > j} wc[b]
    }

    // --- Phase B: branch-free wind += w/(1 + e^{x-xc}); 2-wide via LDS.128 ---
    float wind = 0.0f, wind2 = 0.0f;
    {
        int m = min(s_cnt[wp], CAP);
        const float4* bin4 = (const float4*)&s_bin[wp][0];
        int m2 = m >> 1;
        for (int i = 0; i < m2; ++i) {
            float4 E = bin4[i];                         // two (val,w) entries
            wind  += __fdividef(E.y, fmaf(ex, E.x, 1.0f));
            wind2 += __fdividef(E.w, fmaf(ex, E.z, 1.0f));
        }
        if (m & 1) {
            float2 E = s_bin[wp][m - 1];
            wind += __fdividef(E.y, fmaf(ex, E.x, 1.0f));
        }
    }
    __syncthreads();

    // --- combine + output ---
    wind += wind2 + s_wcs[wp];
    float alpha = fsig(4.0f * wind);
    float cr = __ldg(&color[0]), cg = __ldg(&color[1]), cb = __ldg(&color[2]);
    ((float4*)out)[y * Wd + tid] = make_float4(cr, cg, cb, alpha);
}

extern "C" void kernel_launch(void* const* d_in, const int* in_sizes, int n_in,
                              void* d_out, int out_size) {
    (void)in_sizes; (void)n_in; (void)out_size;
    const float* cp    = (const float*)d_in[0];   // (193,2) float32
    const float* color = (const float*)d_in[1];   // (3,)    float32
    float* out = (float*)d_out;                   // (512,512,4) float32
    render_row<<<Hd, NT>>>(cp, color, out);
}

// round 17
// speedup vs baseline: 1.3892x; 1.0030x over previous
#include <cuda_runtime.h>
#include <math.h>

#define Hd 512
#define Wd 512
#define NSEG 64             // cubic segments
#define NT 512
#define RADIUS 10.0f        // carry/window split half-width
#define E32 7.8962960e13f   // e^{32}
#define NBIN 16             // 32-pixel bins, one per warp
#define CAP 128             // per-bin capacity

__shared__ __align__(16) float2 s_bin[NBIN][CAP];  // 16 KB: (e^{32b - xc}, w)
__shared__ float2 s_cp[194];          // control points (padded to 16B multiple)
__shared__ float2 s_yb[NSEG];         // per-segment conservative row interval
__shared__ int    s_cnt[NBIN];
__shared__ float  s_wc[NBIN + 1];     // full-weight buckets: wc[b] -> warps < b
__shared__ float  s_wcs[NBIN];        // suffix sums: wcs[j] = sum_{b>j} wc[b]

__device__ __forceinline__ float fsig(float z) {
    return __fdividef(1.0f, 1.0f + __expf(-z));
}

// Single fused kernel: one block per row; warp w owns pixels [32w, 32w+31].
__global__ __launch_bounds__(NT)
void render_row(const float* __restrict__ cp,
                const float* __restrict__ color,
                float* __restrict__ out) {
    const int tid  = threadIdx.x;
    const int lane = tid & 31;
    const int wp   = tid >> 5;
    const int y    = blockIdx.x;
    const float gy = (float)y;
    const float2* c2 = (const float2*)cp;

    if (tid < 193) s_cp[tid] = c2[tid];
    if (tid < NBIN) { s_cnt[tid] = 0; s_wc[tid] = 0.0f; }
    if (tid == 0) s_wc[NBIN] = 0.0f;

    // per-segment y-bbox (hull property + band margin)
    if (tid < NSEG) {
        float2 q0 = c2[3 * tid + 0];
        float2 q1 = c2[3 * tid + 1];
        float2 q2 = c2[3 * tid + 2];
        float2 q3 = c2[3 * tid + 3];
        float ymin = fminf(fminf(q0.y, q1.y), fminf(q2.y, q3.y));
        float ymax = fmaxf(fmaxf(q0.y, q1.y), fmaxf(q2.y, q3.y));
        float md = fmaxf(fabsf(q1.y - q0.y),
                   fmaxf(fabsf(q2.y - q1.y), fabsf(q3.y - q2.y)));
        float mg = 0.1f * md + 1.0f;      // need only 0.5*(3*md/31) ~ 0.048*md
        if (tid == NSEG - 1) {            // closing edge to cp[0]
            float yc = c2[0].y;
            ymin = fminf(ymin, yc);
            ymax = fmaxf(ymax, yc);
            mg = fmaxf(mg, 0.5f * fabsf(yc - q3.y) + 1.0f);
        }
        s_yb[tid] = make_float2(ymin - mg, ymax + mg);
    }

    const float ex = __expf((float)lane);               // e^{x - 32*wp}

    // per-lane Bernstein weights at t = lane/31 (same formula as reference)
    const float tb  = (float)lane * (1.0f / 31.0f);
    const float mtb = 1.0f - tb;
    const float bw0 = mtb * mtb * mtb;
    const float bw1 = 3.0f * mtb * mtb * tb;
    const float bw2 = 3.0f * mtb * tb * tb;
    const float bw3 = tb * tb * tb;
    __syncthreads();

    // --- Phase A: warp owns segments 4wp..4wp+3; lane l owns edge 32s+l ---
    #pragma unroll
    for (int it = 0; it < 4; ++it) {
        const int s = (wp << 2) + it;                   // segment 0..63
        float2 yb = s_yb[s];
        if (gy < yb.x || gy > yb.y) continue;           // warp-uniform skip

        float2 P0 = s_cp[3 * s + 0];
        float2 P1 = s_cp[3 * s + 1];
        float2 P2 = s_cp[3 * s + 2];
        float2 P3 = s_cp[3 * s + 3];
        float2 a = make_float2(
            bw0 * P0.x + bw1 * P1.x + bw2 * P2.x + bw3 * P3.x,
            bw0 * P0.y + bw1 * P1.y + bw2 * P2.y + bw3 * P3.y);
        float2 b;
        b.x = __shfl_down_sync(0xffffffffu, a.x, 1);
        b.y = __shfl_down_sync(0xffffffffu, a.y, 1);
        if (lane == 31) b = (s == NSEG - 1) ? s_cp[0] : a;  // closing / degen

        float dy = b.y - a.y;
        if (fabsf(dy) < 1e-6f) continue;                // reference mask==0
        float dyp = dy + 1e-8f;
        float t = (gy - a.y) * __fdividef(1.0f, dyp);
        // band [-0.5, 1.5]: boundary weight sig(-10)=4.5e-5
        if (!(t >= -0.5f && t <= 1.5f)) continue;
        // product of two sigmoids ~= sigmoid of the nearer boundary here
        float w = fsig(20.0f * fminf(t, 1.0f - t));
        w = (dyp > 0.0f) ? w : -w;                      // sign(dy)
        float xc = fmaf(t, b.x - a.x, a.x);

        int b0r = (int)floorf((xc - RADIUS) * (1.0f / 32.0f));
        int b1r = (int)floorf((xc + RADIUS) * (1.0f / 32.0f));
        if (b1r < 0) continue;                          // fully left: zero
        if (b0r >= NBIN) {                              // fully right: all full
            atomicAdd(&s_wc[NBIN], w);
            continue;
        }
        if (b0r > 0) atomicAdd(&s_wc[b0r], w);          // warps < b0r get w
        int b0 = max(b0r, 0);
        int b1 = min(b1r, NBIN - 1);
        float val = __expf((float)(b0 << 5) - xc);      // e^{32*b0 - xc}
        for (int bb = b0; bb <= b1; ++bb) {
            int q = atomicAdd(&s_cnt[bb], 1);
            if (q < CAP) s_bin[bb][q] = make_float2(val, w);
            val *= E32;                                 // next bin: * e^{32}
        }
    }
    __syncthreads();

    // --- warp 0: suffix-scan the 16 buckets while others start Phase B ---
    if (wp == 0 && lane < NBIN) {
        float v = s_wc[lane + 1];
        #pragma unroll
        for (int o = 1; o < NBIN; o <<= 1) {
            float nb = __shfl_down_sync(0x0000ffffu, v, o);
            if (lane + o < NBIN) v += nb;
        }
        s_wcs[lane] = v;            // wcs[j] = sum_{b > j} wc[b]
    }

    // --- Phase B: branch-free wind += w/(1 + e^{x-xc}); 2-wide via LDS.128 ---
    float wind = 0.0f, wind2 = 0.0f;
    {
        int m = min(s_cnt[wp], CAP);
        const float4* bin4 = (const float4*)&s_bin[wp][0];
        int m2 = m >> 1;
        for (int i = 0; i < m2; ++i) {
            float4 E = bin4[i];                         // two (val,w) entries
            wind  += __fdividef(E.y, fmaf(ex, E.x, 1.0f));
            wind2 += __fdividef(E.w, fmaf(ex, E.z, 1.0f));
        }
        if (m & 1) {
            float2 E = s_bin[wp][m - 1];
            wind += __fdividef(E.y, fmaf(ex, E.x, 1.0f));
        }
    }
    __syncthreads();

    // --- combine + output ---
    wind += wind2 + s_wcs[wp];
    float alpha = fsig(4.0f * wind);
    float cr = __ldg(&color[0]), cg = __ldg(&color[1]), cb = __ldg(&color[2]);
    ((float4*)out)[y * Wd + tid] = make_float4(cr, cg, cb, alpha);
}

extern "C" void kernel_launch(void* const* d_in, const int* in_sizes, int n_in,
                              void* d_out, int out_size) {
    (void)in_sizes; (void)n_in; (void)out_size;
    const float* cp    = (const float*)d_in[0];   // (193,2) float32
    const float* color = (const float*)d_in[1];   // (3,)    float32
    float* out = (float*)d_out;                   // (512,512,4) float32
    render_row<<<Hd, NT>>>(cp, color, out);
}